// round 1
// baseline (speedup 1.0000x reference)
#include <cuda_runtime.h>
#include <math.h>

#define PI_D 3.14159265358979323846

#define L1V 2
#define L2V 2
#define LZV 4
#define RB 20
#define RA 19
#define MUL 128
#define NC 128
#define NBATCH 1024
#define D1 9
#define DZ 25
#define GP 28   // padded stride for 25-float rows (112B, 16B aligned)

// -------- device-global scratch (no allocations allowed) --------
__device__ double g_ct[RB];
__device__ double g_qw[RB];
__device__ float  g_Y[DZ * RB * RA];
__device__ float  g_G[81 * GP];   // [pair = i*9+j][d], padded to GP

// -------- compile-time helpers (selection rules) --------
__host__ __device__ constexpr int lof(int d) {
    return (d < 1) ? 0 : (d < 4) ? 1 : (d < 9) ? 2 : (d < 16) ? 3 : 4;
}
__host__ __device__ constexpr int mof(int d) {
    return d - lof(d) * lof(d) - lof(d);
}
__host__ __device__ constexpr bool gaunt_nz(int i, int j, int d) {
    const int l1 = lof(i), m1 = mof(i);
    const int l2 = lof(j), m2 = mof(j);
    const int L  = lof(d), M  = mof(d);
    if ((l1 + l2 + L) & 1) return false;
    const int lo = (l1 > l2) ? (l1 - l2) : (l2 - l1);
    if (L < lo || L > l1 + l2) return false;
    const int f1 = m1 < 0 ? -m1 : m1;
    const int f2 = m2 < 0 ? -m2 : m2;
    const int F  = M  < 0 ? -M  : M;
    const int fd = (f1 > f2) ? (f1 - f2) : (f2 - f1);
    if (!(F == f1 + f2 || F == fd)) return false;
    const int s = (m1 < 0) + (m2 < 0) + (M < 0);
    if (s & 1) return false;
    return true;
}

// -------- init kernel 1: Gauss-Legendre nodes & weights (double Newton) ------
__global__ void init_nodes_kernel() {
    int i = threadIdx.x;
    if (i >= RB) return;
    const int n = RB;
    double x = cos(PI_D * (i + 0.75) / (n + 0.5));
    double pn = 0.0, pnm1 = 0.0;
    for (int it = 0; it < 10; ++it) {
        double p0 = 1.0, p1 = x;
        for (int k = 2; k <= n; ++k) {
            double p = ((2.0 * k - 1.0) * x * p1 - (k - 1.0) * p0) / (double)k;
            p0 = p1; p1 = p;
        }
        pn = p1; pnm1 = p0;
        double dpn = n * (x * pn - pnm1) / (x * x - 1.0);
        x -= pn / dpn;
    }
    // final derivative for weight
    {
        double p0 = 1.0, p1 = x;
        for (int k = 2; k <= n; ++k) {
            double p = ((2.0 * k - 1.0) * x * p1 - (k - 1.0) * p0) / (double)k;
            p0 = p1; p1 = p;
        }
        double dpn = n * (x * p1 - p0) / (x * x - 1.0);
        g_ct[i] = x;
        g_qw[i] = 2.0 / ((1.0 - x * x) * dpn * dpn);
    }
}

// -------- init kernel 2: spherical harmonics table --------
__device__ double dev_assoc_legendre(int l, int m, double x) {
    double pmm = 1.0;
    if (m > 0) {
        double df = 1.0;
        for (int k = 1; k < 2 * m; k += 2) df *= (double)k;
        double s = pow(1.0 - x * x, 0.5 * m);
        pmm = ((m & 1) ? -1.0 : 1.0) * df * s;
    }
    if (l == m) return pmm;
    double pmmp1 = x * (2.0 * m + 1.0) * pmm;
    if (l == m + 1) return pmmp1;
    for (int ll = m + 2; ll <= l; ++ll) {
        double p = ((2.0 * ll - 1.0) * x * pmmp1 - (ll + m - 1.0) * pmm) / (double)(ll - m);
        pmm = pmmp1; pmmp1 = p;
    }
    return pmmp1;
}
__device__ double dev_fact(int k) {
    double f = 1.0;
    for (int v = 2; v <= k; ++v) f *= (double)v;
    return f;
}
__global__ void init_Y_kernel() {
    int idx = blockIdx.x * blockDim.x + threadIdx.x;
    if (idx >= DZ * RB * RA) return;
    int a = idx % RA;
    int b = (idx / RA) % RB;
    int d = idx / (RA * RB);
    int l = lof(d);
    int m = d - l * l - l;
    int am = m < 0 ? -m : m;
    double ct = g_ct[b];
    double alpha = 2.0 * PI_D * (double)a / (double)RA;
    double P = dev_assoc_legendre(l, am, ct);
    double nlm = sqrt((2.0 * l + 1.0) / (4.0 * PI_D) * dev_fact(l - am) / dev_fact(l + am));
    double ang;
    if (m == 0)      ang = 1.0;
    else if (m > 0)  ang = sqrt(2.0) * cos((double)m * alpha);
    else             ang = sqrt(2.0) * sin((double)am * alpha);
    g_Y[idx] = (float)(nlm * P * ang);
}

// -------- init kernel 3: Gaunt tensor G[pair][d] --------
// Folds the xc*yc 1/sqrt(MUL)*1/sqrt(MUL) = 1/128 scale and the 2*pi/RA factor.
__global__ void init_G_kernel() {
    int pair = blockIdx.x;      // 0..80
    int d = threadIdx.x;        // 0..31
    if (pair >= 81) return;
    int i = pair / 9, j = pair % 9;
    if (d < GP && d >= DZ) { g_G[pair * GP + d] = 0.0f; return; }
    if (d >= DZ) return;
    const float* Yi = g_Y + i * RB * RA;
    const float* Yj = g_Y + j * RB * RA;
    const float* Yd = g_Y + d * RB * RA;
    float s = 0.0f;
    for (int b = 0; b < RB; ++b) {
        float w = (float)g_qw[b];
        float sb = 0.0f;
        #pragma unroll
        for (int a = 0; a < RA; ++a) {
            int o = b * RA + a;
            sb += Yi[o] * Yj[o] * Yd[o];
        }
        s += sb * w;
    }
    const float scale = (float)(2.0 * PI_D / (double)RA) / (float)MUL;
    g_G[pair * GP + d] = s * scale;
}

// -------- main fused kernel: one block per n, one thread per channel --------
__global__ void __launch_bounds__(128)
gaunt_main_kernel(const float* __restrict__ x, const float* __restrict__ y,
                  const float* __restrict__ wx, const float* __restrict__ wy,
                  const float* __restrict__ wz, float* __restrict__ out) {
    __shared__ __align__(16) float xs[MUL * 12];
    __shared__ __align__(16) float ys[MUL * 12];
    __shared__ __align__(16) float Gs[81 * GP];
    __shared__ __align__(16) float zs[NC * GP];

    const int n = blockIdx.x;
    const int c = threadIdx.x;

    // cooperative stage-in
    const float* xg = x + (size_t)n * MUL * D1;
    const float* yg = y + (size_t)n * MUL * D1;
    for (int idx = c; idx < MUL * D1; idx += 128) {
        int m = idx / 9, dd = idx - m * 9;
        xs[m * 12 + dd] = xg[idx];
        ys[m * 12 + dd] = yg[idx];
    }
    for (int idx = c; idx < 81 * GP; idx += 128) Gs[idx] = g_G[idx];
    __syncthreads();

    // ---- stage 1: per-l linear in  (xc, yc per channel c) ----
    float xc[9], yc[9];
    #pragma unroll
    for (int d = 0; d < 9; ++d) { xc[d] = 0.0f; yc[d] = 0.0f; }

    #pragma unroll 4
    for (int m = 0; m < MUL; ++m) {
        float wx0 = wx[m * NC + c];
        float wx1 = wx[(MUL + m) * NC + c];
        float wx2 = wx[(2 * MUL + m) * NC + c];
        float wy0 = wy[m * NC + c];
        float wy1 = wy[(MUL + m) * NC + c];
        float wy2 = wy[(2 * MUL + m) * NC + c];
        float4 xv0 = *(const float4*)&xs[m * 12];
        float4 xv1 = *(const float4*)&xs[m * 12 + 4];
        float  xv8 = xs[m * 12 + 8];
        float4 yv0 = *(const float4*)&ys[m * 12];
        float4 yv1 = *(const float4*)&ys[m * 12 + 4];
        float  yv8 = ys[m * 12 + 8];
        xc[0] += xv0.x * wx0;
        xc[1] += xv0.y * wx1; xc[2] += xv0.z * wx1; xc[3] += xv0.w * wx1;
        xc[4] += xv1.x * wx2; xc[5] += xv1.y * wx2; xc[6] += xv1.z * wx2;
        xc[7] += xv1.w * wx2; xc[8] += xv8   * wx2;
        yc[0] += yv0.x * wy0;
        yc[1] += yv0.y * wy1; yc[2] += yv0.z * wy1; yc[3] += yv0.w * wy1;
        yc[4] += yv1.x * wy2; yc[5] += yv1.y * wy2; yc[6] += yv1.z * wy2;
        yc[7] += yv1.w * wy2; yc[8] += yv8   * wy2;
    }

    // ---- stage 2: sparse Gaunt contraction z_d = sum_ij xc_i yc_j G[d,i,j] ----
    float z[DZ];
    #pragma unroll
    for (int d = 0; d < DZ; ++d) z[d] = 0.0f;

    #pragma unroll
    for (int i = 0; i < 9; ++i) {
        #pragma unroll
        for (int j = 0; j < 9; ++j) {
            float p = xc[i] * yc[j];
            #pragma unroll
            for (int d = 0; d < DZ; ++d) {
                if (gaunt_nz(i, j, d)) {            // compile-time constant after unroll
                    z[d] += p * Gs[(i * 9 + j) * GP + d];
                }
            }
        }
    }

    // ---- stage 3: per-l channel mixing out[n,e,d] = sum_c z[n,c,d] wz[l,c,e] ----
    #pragma unroll
    for (int d = 0; d < DZ; ++d) zs[c * GP + d] = z[d];
    __syncthreads();

    float acc[DZ];
    #pragma unroll
    for (int d = 0; d < DZ; ++d) acc[d] = 0.0f;

    #pragma unroll 2
    for (int cc = 0; cc < NC; ++cc) {
        float w0 = wz[cc * NC + c];
        float w1 = wz[(NC     + cc) * NC + c];
        float w2 = wz[(2 * NC + cc) * NC + c];
        float w3 = wz[(3 * NC + cc) * NC + c];
        float w4 = wz[(4 * NC + cc) * NC + c];
        const float* zp = &zs[cc * GP];
        float4 z0 = *(const float4*)(zp);
        float4 z1 = *(const float4*)(zp + 4);
        float4 z2 = *(const float4*)(zp + 8);
        float4 z3 = *(const float4*)(zp + 12);
        float4 z4 = *(const float4*)(zp + 16);
        float4 z5 = *(const float4*)(zp + 20);
        float  z6 = zp[24];
        acc[0]  += z0.x * w0;
        acc[1]  += z0.y * w1; acc[2]  += z0.z * w1; acc[3]  += z0.w * w1;
        acc[4]  += z1.x * w2; acc[5]  += z1.y * w2; acc[6]  += z1.z * w2;
        acc[7]  += z1.w * w2; acc[8]  += z2.x * w2;
        acc[9]  += z2.y * w3; acc[10] += z2.z * w3; acc[11] += z2.w * w3;
        acc[12] += z3.x * w3; acc[13] += z3.y * w3; acc[14] += z3.z * w3;
        acc[15] += z3.w * w3;
        acc[16] += z4.x * w4; acc[17] += z4.y * w4; acc[18] += z4.z * w4;
        acc[19] += z4.w * w4; acc[20] += z5.x * w4; acc[21] += z5.y * w4;
        acc[22] += z5.z * w4; acc[23] += z5.w * w4; acc[24] += z6   * w4;
    }

    const float s_out = 0.08838834764831845f;  // 1/sqrt(128)
    float* og = out + ((size_t)n * NC + c) * DZ;
    #pragma unroll
    for (int d = 0; d < DZ; ++d) og[d] = acc[d] * s_out;
}

extern "C" void kernel_launch(void* const* d_in, const int* in_sizes, int n_in,
                              void* d_out, int out_size) {
    const float* x  = (const float*)d_in[0];
    const float* y  = (const float*)d_in[1];
    const float* wx = (const float*)d_in[2];
    const float* wy = (const float*)d_in[3];
    const float* wz = (const float*)d_in[4];
    float* out = (float*)d_out;

    init_nodes_kernel<<<1, 32>>>();
    init_Y_kernel<<<(DZ * RB * RA + 255) / 256, 256>>>();
    init_G_kernel<<<81, 32>>>();
    gaunt_main_kernel<<<NBATCH, 128>>>(x, y, wx, wy, wz, out);
}

// round 3
// speedup vs baseline: 2.2888x; 2.2888x over previous
#include <cuda_runtime.h>
#include <math.h>

#define PI_D 3.14159265358979323846

#define RB 20
#define RA 19
#define MUL 128
#define NC 128
#define NBATCH 1024
#define D1 9
#define DZ 25
#define GP 30          // padded stride for 25-float rows (120B, 8B aligned)
#define TILE_N 2

// -------- Gaunt table passed by value in kernel-param space --------
struct GTab { float v[81 * GP]; };   // 9720 bytes

// -------- compile-time selection rules --------
__host__ __device__ constexpr int lof(int d) {
    return (d < 1) ? 0 : (d < 4) ? 1 : (d < 9) ? 2 : (d < 16) ? 3 : 4;
}
__host__ __device__ constexpr bool gaunt_nz(int i, int j, int d) {
    const int l1 = lof(i), m1 = i - l1 * l1 - l1;
    const int l2 = lof(j), m2 = j - l2 * l2 - l2;
    const int L  = lof(d), M  = d - L * L - L;
    if ((l1 + l2 + L) & 1) return false;
    const int lo = (l1 > l2) ? (l1 - l2) : (l2 - l1);
    if (L < lo || L > l1 + l2) return false;
    const int f1 = m1 < 0 ? -m1 : m1;
    const int f2 = m2 < 0 ? -m2 : m2;
    const int F  = M  < 0 ? -M  : M;
    const int fd = (f1 > f2) ? (f1 - f2) : (f2 - f1);
    if (!(F == f1 + f2 || F == fd)) return false;
    if (((m1 < 0) + (m2 < 0) + (M < 0)) & 1) return false;
    return true;
}

// -------- packed f32x2 helpers --------
__device__ __forceinline__ unsigned long long pk2(float lo, float hi) {
    unsigned long long r;
    asm("mov.b64 %0, {%1, %2};" : "=l"(r) : "f"(lo), "f"(hi));
    return r;
}
__device__ __forceinline__ void ffma2(unsigned long long& d,
                                      unsigned long long a, unsigned long long b) {
    asm("fma.rn.f32x2 %0, %1, %2, %0;" : "+l"(d) : "l"(a), "l"(b));
}
__device__ __forceinline__ void unpk2(unsigned long long v, float& lo, float& hi) {
    asm("mov.b64 {%0, %1}, %2;" : "=f"(lo), "=f"(hi) : "l"(v));
}

// -------- sparse Gaunt contraction (compile-time-pruned) --------
__device__ __forceinline__ void gaunt_contract(const float* __restrict__ xc,
                                               const float* __restrict__ yc,
                                               const float* __restrict__ Gs,
                                               float* __restrict__ z) {
    #pragma unroll
    for (int d = 0; d < DZ; ++d) z[d] = 0.0f;
    #pragma unroll
    for (int i = 0; i < 9; ++i) {
        #pragma unroll
        for (int j = 0; j < 9; ++j) {
            float p = xc[i] * yc[j];
            #pragma unroll
            for (int d = 0; d < DZ; ++d) {
                if (gaunt_nz(i, j, d)) {
                    z[d] += p * Gs[(i * 9 + j) * GP + d];
                }
            }
        }
    }
}

// per-node, per-input stage-1 inner step:
// smem row layout: [d1..d8, d0, pad, pad, pad] (stride 12)
// acc: A[0]=(c1,c2)*wb, A[1]=(c3,c4)*(wb,wc), A[2]=(c5,c6)*wc, A[3]=(c7,c8)*wc, s += d0*wa
__device__ __forceinline__ void s1_step(const float* __restrict__ row,
                                        unsigned long long pbb,
                                        unsigned long long pbc,
                                        unsigned long long pcc,
                                        float wa,
                                        unsigned long long* __restrict__ A,
                                        float& s) {
    float4 v0 = *(const float4*)(row);      // d1..d4
    float4 v1 = *(const float4*)(row + 4);  // d5..d8
    float  v8 = row[8];                     // d0
    ffma2(A[0], pk2(v0.x, v0.y), pbb);
    ffma2(A[1], pk2(v0.z, v0.w), pbc);
    ffma2(A[2], pk2(v1.x, v1.y), pcc);
    ffma2(A[3], pk2(v1.z, v1.w), pcc);
    s += v8 * wa;
}

// -------- main fused kernel: one block per 2 nodes, one thread per channel ----
__global__ void __launch_bounds__(128, 4)
gaunt_main_kernel(const float* __restrict__ x, const float* __restrict__ y,
                  const float* __restrict__ wx, const float* __restrict__ wy,
                  const float* __restrict__ wz, float* __restrict__ out,
                  const __grid_constant__ GTab G) {
    __shared__ __align__(16) float Gs[81 * GP];              // 9720 B
    __shared__ __align__(16) float pool[TILE_N * NC * GP];   // 30720 B (xs/ys then zs)

    const int c = threadIdx.x;
    const int n0 = blockIdx.x * TILE_N;

    float* xs0 = pool;               // 128 rows * 12
    float* ys0 = pool + 1536;
    float* xs1 = pool + 3072;
    float* ys1 = pool + 4608;

    // ---- cooperative stage-in (remap d -> [d1..d8, d0]) ----
    const float* xg0 = x + (size_t)n0 * MUL * D1;
    const float* yg0 = y + (size_t)n0 * MUL * D1;
    const float* xg1 = xg0 + MUL * D1;
    const float* yg1 = yg0 + MUL * D1;
    for (int idx = c; idx < MUL * D1; idx += 128) {
        int m = idx / 9, dd = idx - m * 9;
        int k = (dd == 0) ? 8 : (dd - 1);
        xs0[m * 12 + k] = xg0[idx];
        ys0[m * 12 + k] = yg0[idx];
        xs1[m * 12 + k] = xg1[idx];
        ys1[m * 12 + k] = yg1[idx];
    }
    // G table param -> smem as float2
    for (int idx = c; idx < (81 * GP) / 2; idx += 128) {
        ((float2*)Gs)[idx] = ((const float2*)G.v)[idx];
    }
    __syncthreads();

    // ---- stage 1: per-l linear in for both nodes (packed f32x2) ----
    unsigned long long Ax0[4], Ay0[4], Ax1[4], Ay1[4];
    float sx0 = 0.0f, sy0 = 0.0f, sx1 = 0.0f, sy1 = 0.0f;
    #pragma unroll
    for (int k = 0; k < 4; ++k) { Ax0[k] = Ay0[k] = Ax1[k] = Ay1[k] = 0ULL; }

    #pragma unroll 2
    for (int m = 0; m < MUL; ++m) {
        float wxa = wx[m * NC + c];
        float wxb = wx[(MUL + m) * NC + c];
        float wxcv = wx[(2 * MUL + m) * NC + c];
        float wya = wy[m * NC + c];
        float wyb = wy[(MUL + m) * NC + c];
        float wycv = wy[(2 * MUL + m) * NC + c];

        unsigned long long pxbb = pk2(wxb, wxb);
        unsigned long long pxbc = pk2(wxb, wxcv);
        unsigned long long pxcc = pk2(wxcv, wxcv);
        unsigned long long pybb = pk2(wyb, wyb);
        unsigned long long pybc = pk2(wyb, wycv);
        unsigned long long pycc = pk2(wycv, wycv);

        s1_step(&xs0[m * 12], pxbb, pxbc, pxcc, wxa, Ax0, sx0);
        s1_step(&ys0[m * 12], pybb, pybc, pycc, wya, Ay0, sy0);
        s1_step(&xs1[m * 12], pxbb, pxbc, pxcc, wxa, Ax1, sx1);
        s1_step(&ys1[m * 12], pybb, pybc, pycc, wya, Ay1, sy1);
    }

    // unpack to scalar xc/yc (index = real d)
    float xc0[9], yc0[9], xc1[9], yc1[9];
    xc0[0] = sx0; yc0[0] = sy0; xc1[0] = sx1; yc1[0] = sy1;
    #pragma unroll
    for (int k = 0; k < 4; ++k) {
        unpk2(Ax0[k], xc0[2 * k + 1], xc0[2 * k + 2]);
        unpk2(Ay0[k], yc0[2 * k + 1], yc0[2 * k + 2]);
        unpk2(Ax1[k], xc1[2 * k + 1], xc1[2 * k + 2]);
        unpk2(Ay1[k], yc1[2 * k + 1], yc1[2 * k + 2]);
    }

    // ---- stage 2: sparse Gaunt contraction (registers only) ----
    float z0[DZ], z1[DZ];
    gaunt_contract(xc0, yc0, Gs, z0);
    gaunt_contract(xc1, yc1, Gs, z1);

    __syncthreads();   // everyone done reading xs/ys before zs overwrites pool

    float* zs0 = pool;                 // 128 rows * GP
    float* zs1 = pool + NC * GP;
    #pragma unroll
    for (int d = 0; d < DZ; ++d) { zs0[c * GP + d] = z0[d]; zs1[c * GP + d] = z1[d]; }
    __syncthreads();

    // ---- stage 3: per-l channel mixing, packed f32x2 ----
    unsigned long long a0[12], a1[12];
    float a0s = 0.0f, a1s = 0.0f;
    #pragma unroll
    for (int k = 0; k < 12; ++k) { a0[k] = 0ULL; a1[k] = 0ULL; }

    #pragma unroll 2
    for (int cc = 0; cc < NC; ++cc) {
        float w0 = wz[cc * NC + c];
        float w1 = wz[(NC + cc) * NC + c];
        float w2 = wz[(2 * NC + cc) * NC + c];
        float w3 = wz[(3 * NC + cc) * NC + c];
        float w4 = wz[(4 * NC + cc) * NC + c];

        unsigned long long p01 = pk2(w0, w1);
        unsigned long long p11 = pk2(w1, w1);
        unsigned long long p22 = pk2(w2, w2);
        unsigned long long p23 = pk2(w2, w3);
        unsigned long long p33 = pk2(w3, w3);
        unsigned long long p44 = pk2(w4, w4);

        const unsigned long long* zp0 = (const unsigned long long*)(zs0 + cc * GP);
        const unsigned long long* zp1 = (const unsigned long long*)(zs1 + cc * GP);

        ffma2(a0[0], zp0[0], p01);
        ffma2(a0[1], zp0[1], p11);
        ffma2(a0[2], zp0[2], p22);
        ffma2(a0[3], zp0[3], p22);
        ffma2(a0[4], zp0[4], p23);
        ffma2(a0[5], zp0[5], p33);
        ffma2(a0[6], zp0[6], p33);
        ffma2(a0[7], zp0[7], p33);
        ffma2(a0[8], zp0[8], p44);
        ffma2(a0[9], zp0[9], p44);
        ffma2(a0[10], zp0[10], p44);
        ffma2(a0[11], zp0[11], p44);
        a0s += zs0[cc * GP + 24] * w4;

        ffma2(a1[0], zp1[0], p01);
        ffma2(a1[1], zp1[1], p11);
        ffma2(a1[2], zp1[2], p22);
        ffma2(a1[3], zp1[3], p22);
        ffma2(a1[4], zp1[4], p23);
        ffma2(a1[5], zp1[5], p33);
        ffma2(a1[6], zp1[6], p33);
        ffma2(a1[7], zp1[7], p33);
        ffma2(a1[8], zp1[8], p44);
        ffma2(a1[9], zp1[9], p44);
        ffma2(a1[10], zp1[10], p44);
        ffma2(a1[11], zp1[11], p44);
        a1s += zs1[cc * GP + 24] * w4;
    }

    // ---- write out (all scalar factors folded into G on host) ----
    float* og0 = out + ((size_t)n0 * NC + c) * DZ;
    float* og1 = og0 + (size_t)NC * DZ;
    #pragma unroll
    for (int k = 0; k < 12; ++k) {
        float lo, hi;
        unpk2(a0[k], lo, hi);
        og0[2 * k] = lo; og0[2 * k + 1] = hi;
        unpk2(a1[k], lo, hi);
        og1[2 * k] = lo; og1[2 * k + 1] = hi;
    }
    og0[24] = a0s;
    og1[24] = a1s;
}

// ===================== host-side Gaunt table computation =====================
static GTab h_G;

static double h_assoc_legendre(int l, int m, double x) {
    double pmm = 1.0;
    if (m > 0) {
        double df = 1.0;
        for (int k = 1; k < 2 * m; k += 2) df *= (double)k;
        pmm = ((m & 1) ? -1.0 : 1.0) * df * pow(1.0 - x * x, 0.5 * m);
    }
    if (l == m) return pmm;
    double pmmp1 = x * (2.0 * m + 1.0) * pmm;
    if (l == m + 1) return pmmp1;
    for (int ll = m + 2; ll <= l; ++ll) {
        double p = ((2.0 * ll - 1.0) * x * pmmp1 - (ll + m - 1.0) * pmm) / (double)(ll - m);
        pmm = pmmp1; pmmp1 = p;
    }
    return pmmp1;
}
static double h_fact(int k) { double f = 1.0; for (int v = 2; v <= k; ++v) f *= v; return f; }

static void host_compute_G() {
    // Gauss-Legendre nodes/weights (Newton, double)
    double ct[RB], qw[RB];
    for (int i = 0; i < RB; ++i) {
        double xv = cos(PI_D * (i + 0.75) / (RB + 0.5));
        double p0 = 1.0, p1 = xv, dp = 0.0;
        for (int it = 0; it < 100; ++it) {
            p0 = 1.0; p1 = xv;
            for (int k = 2; k <= RB; ++k) {
                double p = ((2.0 * k - 1.0) * xv * p1 - (k - 1.0) * p0) / (double)k;
                p0 = p1; p1 = p;
            }
            dp = RB * (xv * p1 - p0) / (xv * xv - 1.0);
            double dx = p1 / dp;
            xv -= dx;
            if (fabs(dx) < 1e-15) {
                p0 = 1.0; p1 = xv;
                for (int k = 2; k <= RB; ++k) {
                    double p = ((2.0 * k - 1.0) * xv * p1 - (k - 1.0) * p0) / (double)k;
                    p0 = p1; p1 = p;
                }
                dp = RB * (xv * p1 - p0) / (xv * xv - 1.0);
                break;
            }
        }
        ct[i] = xv;
        qw[i] = 2.0 / ((1.0 - xv * xv) * dp * dp);
    }

    // Y table (double)
    static double Y[DZ][RB][RA];
    for (int d = 0; d < DZ; ++d) {
        int l = lof(d);
        int m = d - l * l - l;
        int am = m < 0 ? -m : m;
        double nlm = sqrt((2.0 * l + 1.0) / (4.0 * PI_D) * h_fact(l - am) / h_fact(l + am));
        for (int b = 0; b < RB; ++b) {
            double P = h_assoc_legendre(l, am, ct[b]);
            for (int a = 0; a < RA; ++a) {
                double alpha = 2.0 * PI_D * (double)a / (double)RA;
                double ang;
                if (m == 0)      ang = 1.0;
                else if (m > 0)  ang = sqrt(2.0) * cos((double)m * alpha);
                else             ang = sqrt(2.0) * sin((double)am * alpha);
                Y[d][b][a] = nlm * P * ang;
            }
        }
    }

    // G[pair][d] with ALL scalar factors folded:
    //   (2*pi/RA) quadrature * (1/sqrt(MUL))^2 input linears * (1/sqrt(NC)) output linear
    const double scale = (2.0 * PI_D / (double)RA) / (double)MUL / sqrt((double)NC);
    for (int i = 0; i < 9; ++i) {
        for (int j = 0; j < 9; ++j) {
            for (int d = 0; d < GP; ++d) {
                double s = 0.0;
                if (d < DZ) {
                    for (int b = 0; b < RB; ++b) {
                        double sb = 0.0;
                        for (int a = 0; a < RA; ++a)
                            sb += Y[i][b][a] * Y[j][b][a] * Y[d][b][a];
                        s += sb * qw[b];
                    }
                }
                h_G.v[(i * 9 + j) * GP + d] = (float)(s * scale);
            }
        }
    }
}

extern "C" void kernel_launch(void* const* d_in, const int* in_sizes, int n_in,
                              void* d_out, int out_size) {
    const float* x  = (const float*)d_in[0];
    const float* y  = (const float*)d_in[1];
    const float* wx = (const float*)d_in[2];
    const float* wy = (const float*)d_in[3];
    const float* wz = (const float*)d_in[4];
    float* out = (float*)d_out;

    host_compute_G();  // pure host math, deterministic, runs on every call
    gaunt_main_kernel<<<NBATCH / TILE_N, 128>>>(x, y, wx, wy, wz, out, h_G);
}

// round 4
// speedup vs baseline: 2.3300x; 1.0180x over previous
#include <cuda_runtime.h>
#include <math.h>

#define PI_D 3.14159265358979323846

#define RB 20
#define RA 19
#define MUL 128
#define NC 128
#define NBATCH 1024
#define D1 9
#define DZ 25
#define GP 30          // padded stride for 25-float rows (120B, 8B aligned)

// -------- Gaunt table passed by value in kernel-param space --------
struct GTab { float v[81 * GP]; };   // 9720 bytes

// -------- compile-time selection rules --------
__host__ __device__ constexpr int lof(int d) {
    return (d < 1) ? 0 : (d < 4) ? 1 : (d < 9) ? 2 : (d < 16) ? 3 : 4;
}
__host__ __device__ constexpr bool gaunt_nz(int i, int j, int d) {
    const int l1 = lof(i), m1 = i - l1 * l1 - l1;
    const int l2 = lof(j), m2 = j - l2 * l2 - l2;
    const int L  = lof(d), M  = d - L * L - L;
    if ((l1 + l2 + L) & 1) return false;
    const int lo = (l1 > l2) ? (l1 - l2) : (l2 - l1);
    if (L < lo || L > l1 + l2) return false;
    const int f1 = m1 < 0 ? -m1 : m1;
    const int f2 = m2 < 0 ? -m2 : m2;
    const int F  = M  < 0 ? -M  : M;
    const int fd = (f1 > f2) ? (f1 - f2) : (f2 - f1);
    if (!(F == f1 + f2 || F == fd)) return false;
    if (((m1 < 0) + (m2 < 0) + (M < 0)) & 1) return false;
    return true;
}

// -------- packed f32x2 helpers --------
__device__ __forceinline__ unsigned long long pk2(float lo, float hi) {
    unsigned long long r;
    asm("mov.b64 %0, {%1, %2};" : "=l"(r) : "f"(lo), "f"(hi));
    return r;
}
__device__ __forceinline__ void ffma2(unsigned long long& d,
                                      unsigned long long a, unsigned long long b) {
    asm("fma.rn.f32x2 %0, %1, %2, %0;" : "+l"(d) : "l"(a), "l"(b));
}
__device__ __forceinline__ void unpk2(unsigned long long v, float& lo, float& hi) {
    asm("mov.b64 {%0, %1}, %2;" : "=f"(lo), "=f"(hi) : "l"(v));
}

// -------- sparse Gaunt contraction (compile-time-pruned) --------
__device__ __forceinline__ void gaunt_contract(const float* __restrict__ xc,
                                               const float* __restrict__ yc,
                                               const float* __restrict__ Gs,
                                               float* __restrict__ z) {
    #pragma unroll
    for (int d = 0; d < DZ; ++d) z[d] = 0.0f;
    #pragma unroll
    for (int i = 0; i < 9; ++i) {
        #pragma unroll
        for (int j = 0; j < 9; ++j) {
            float p = xc[i] * yc[j];
            #pragma unroll
            for (int d = 0; d < DZ; ++d) {
                if (gaunt_nz(i, j, d)) {
                    z[d] += p * Gs[(i * 9 + j) * GP + d];
                }
            }
        }
    }
}

// -------- main fused kernel: one block per node, one thread per channel ----
__global__ void __launch_bounds__(128, 7)
gaunt_main_kernel(const float* __restrict__ x, const float* __restrict__ y,
                  const float* __restrict__ wx, const float* __restrict__ wy,
                  const float* __restrict__ wz, float* __restrict__ out,
                  const __grid_constant__ GTab G) {
    __shared__ __align__(16) float Gs[81 * GP];      // 9720 B
    __shared__ __align__(16) float pool[NC * GP];    // 15360 B (xs/ys then zs)

    const int c = threadIdx.x;
    const int n = blockIdx.x;

    float* xs = pool;           // 128 rows * 12 (layout [d1..d8, d0, pad*3])
    float* ys = pool + 1536;

    // ---- cooperative stage-in (remap d -> [d1..d8, d0]) ----
    const float* xg = x + (size_t)n * MUL * D1;
    const float* yg = y + (size_t)n * MUL * D1;
    #pragma unroll
    for (int it = 0; it < 9; ++it) {
        int idx = c + it * 128;
        int m = idx / 9, dd = idx - m * 9;
        int k = (dd == 0) ? 8 : (dd - 1);
        xs[m * 12 + k] = xg[idx];
        ys[m * 12 + k] = yg[idx];
    }
    // G table param -> smem as float2
    for (int idx = c; idx < (81 * GP) / 2; idx += 128) {
        ((float2*)Gs)[idx] = ((const float2*)G.v)[idx];
    }
    __syncthreads();

    // ---- stage 1: per-l linear in (packed f32x2) ----
    unsigned long long Ax[4], Ay[4];
    float sx = 0.0f, sy = 0.0f;
    #pragma unroll
    for (int k = 0; k < 4; ++k) { Ax[k] = Ay[k] = 0ULL; }

    #pragma unroll 4
    for (int m = 0; m < MUL; ++m) {
        float wxa = wx[m * NC + c];
        float wxb = wx[(MUL + m) * NC + c];
        float wxcv = wx[(2 * MUL + m) * NC + c];
        float wya = wy[m * NC + c];
        float wyb = wy[(MUL + m) * NC + c];
        float wycv = wy[(2 * MUL + m) * NC + c];

        {
            float4 v0 = *(const float4*)&xs[m * 12];      // d1..d4
            float4 v1 = *(const float4*)&xs[m * 12 + 4];  // d5..d8
            float  v8 = xs[m * 12 + 8];                   // d0
            ffma2(Ax[0], pk2(v0.x, v0.y), pk2(wxb, wxb));
            ffma2(Ax[1], pk2(v0.z, v0.w), pk2(wxb, wxcv));
            ffma2(Ax[2], pk2(v1.x, v1.y), pk2(wxcv, wxcv));
            ffma2(Ax[3], pk2(v1.z, v1.w), pk2(wxcv, wxcv));
            sx += v8 * wxa;
        }
        {
            float4 v0 = *(const float4*)&ys[m * 12];
            float4 v1 = *(const float4*)&ys[m * 12 + 4];
            float  v8 = ys[m * 12 + 8];
            ffma2(Ay[0], pk2(v0.x, v0.y), pk2(wyb, wyb));
            ffma2(Ay[1], pk2(v0.z, v0.w), pk2(wyb, wycv));
            ffma2(Ay[2], pk2(v1.x, v1.y), pk2(wycv, wycv));
            ffma2(Ay[3], pk2(v1.z, v1.w), pk2(wycv, wycv));
            sy += v8 * wya;
        }
    }

    // unpack to scalar xc/yc (index = real d)
    float xc[9], yc[9];
    xc[0] = sx; yc[0] = sy;
    #pragma unroll
    for (int k = 0; k < 4; ++k) {
        unpk2(Ax[k], xc[2 * k + 1], xc[2 * k + 2]);
        unpk2(Ay[k], yc[2 * k + 1], yc[2 * k + 2]);
    }

    // ---- stage 2: sparse Gaunt contraction (registers only) ----
    float z[DZ];
    gaunt_contract(xc, yc, Gs, z);

    __syncthreads();   // everyone done reading xs/ys before zs overwrites pool

    float* zs = pool;  // 128 rows * GP
    #pragma unroll
    for (int d = 0; d < DZ; ++d) zs[c * GP + d] = z[d];
    __syncthreads();

    // ---- stage 3: per-l channel mixing, packed f32x2 ----
    unsigned long long a[12];
    float as = 0.0f;
    #pragma unroll
    for (int k = 0; k < 12; ++k) a[k] = 0ULL;

    #pragma unroll 4
    for (int cc = 0; cc < NC; ++cc) {
        float w0 = wz[cc * NC + c];
        float w1 = wz[(NC + cc) * NC + c];
        float w2 = wz[(2 * NC + cc) * NC + c];
        float w3 = wz[(3 * NC + cc) * NC + c];
        float w4 = wz[(4 * NC + cc) * NC + c];

        unsigned long long p01 = pk2(w0, w1);
        unsigned long long p11 = pk2(w1, w1);
        unsigned long long p22 = pk2(w2, w2);
        unsigned long long p23 = pk2(w2, w3);
        unsigned long long p33 = pk2(w3, w3);
        unsigned long long p44 = pk2(w4, w4);

        const unsigned long long* zp = (const unsigned long long*)(zs + cc * GP);

        ffma2(a[0], zp[0], p01);
        ffma2(a[1], zp[1], p11);
        ffma2(a[2], zp[2], p22);
        ffma2(a[3], zp[3], p22);
        ffma2(a[4], zp[4], p23);
        ffma2(a[5], zp[5], p33);
        ffma2(a[6], zp[6], p33);
        ffma2(a[7], zp[7], p33);
        ffma2(a[8], zp[8], p44);
        ffma2(a[9], zp[9], p44);
        ffma2(a[10], zp[10], p44);
        ffma2(a[11], zp[11], p44);
        as += zs[cc * GP + 24] * w4;
    }

    // ---- write out (all scalar factors folded into G on host) ----
    float* og = out + ((size_t)n * NC + c) * DZ;
    #pragma unroll
    for (int k = 0; k < 12; ++k) {
        float lo, hi;
        unpk2(a[k], lo, hi);
        og[2 * k] = lo; og[2 * k + 1] = hi;
    }
    og[24] = as;
}

// ===================== host-side Gaunt table computation =====================
static GTab h_G;

static double h_assoc_legendre(int l, int m, double x) {
    double pmm = 1.0;
    if (m > 0) {
        double df = 1.0;
        for (int k = 1; k < 2 * m; k += 2) df *= (double)k;
        pmm = ((m & 1) ? -1.0 : 1.0) * df * pow(1.0 - x * x, 0.5 * m);
    }
    if (l == m) return pmm;
    double pmmp1 = x * (2.0 * m + 1.0) * pmm;
    if (l == m + 1) return pmmp1;
    for (int ll = m + 2; ll <= l; ++ll) {
        double p = ((2.0 * ll - 1.0) * x * pmmp1 - (ll + m - 1.0) * pmm) / (double)(ll - m);
        pmm = pmmp1; pmmp1 = p;
    }
    return pmmp1;
}
static double h_fact(int k) { double f = 1.0; for (int v = 2; v <= k; ++v) f *= v; return f; }

static void host_compute_G() {
    double ct[RB], qw[RB];
    for (int i = 0; i < RB; ++i) {
        double xv = cos(PI_D * (i + 0.75) / (RB + 0.5));
        double p0 = 1.0, p1 = xv, dp = 0.0;
        for (int it = 0; it < 100; ++it) {
            p0 = 1.0; p1 = xv;
            for (int k = 2; k <= RB; ++k) {
                double p = ((2.0 * k - 1.0) * xv * p1 - (k - 1.0) * p0) / (double)k;
                p0 = p1; p1 = p;
            }
            dp = RB * (xv * p1 - p0) / (xv * xv - 1.0);
            double dx = p1 / dp;
            xv -= dx;
            if (fabs(dx) < 1e-15) {
                p0 = 1.0; p1 = xv;
                for (int k = 2; k <= RB; ++k) {
                    double p = ((2.0 * k - 1.0) * xv * p1 - (k - 1.0) * p0) / (double)k;
                    p0 = p1; p1 = p;
                }
                dp = RB * (xv * p1 - p0) / (xv * xv - 1.0);
                break;
            }
        }
        ct[i] = xv;
        qw[i] = 2.0 / ((1.0 - xv * xv) * dp * dp);
    }

    static double Y[DZ][RB][RA];
    for (int d = 0; d < DZ; ++d) {
        int l = lof(d);
        int m = d - l * l - l;
        int am = m < 0 ? -m : m;
        double nlm = sqrt((2.0 * l + 1.0) / (4.0 * PI_D) * h_fact(l - am) / h_fact(l + am));
        for (int b = 0; b < RB; ++b) {
            double P = h_assoc_legendre(l, am, ct[b]);
            for (int a = 0; a < RA; ++a) {
                double alpha = 2.0 * PI_D * (double)a / (double)RA;
                double ang;
                if (m == 0)      ang = 1.0;
                else if (m > 0)  ang = sqrt(2.0) * cos((double)m * alpha);
                else             ang = sqrt(2.0) * sin((double)am * alpha);
                Y[d][b][a] = nlm * P * ang;
            }
        }
    }

    // (2*pi/RA) quadrature * (1/sqrt(MUL))^2 input linears * (1/sqrt(NC)) output linear
    const double scale = (2.0 * PI_D / (double)RA) / (double)MUL / sqrt((double)NC);
    for (int i = 0; i < 9; ++i) {
        for (int j = 0; j < 9; ++j) {
            for (int d = 0; d < GP; ++d) {
                double s = 0.0;
                if (d < DZ) {
                    for (int b = 0; b < RB; ++b) {
                        double sb = 0.0;
                        for (int a = 0; a < RA; ++a)
                            sb += Y[i][b][a] * Y[j][b][a] * Y[d][b][a];
                        s += sb * qw[b];
                    }
                }
                h_G.v[(i * 9 + j) * GP + d] = (float)(s * scale);
            }
        }
    }
}

extern "C" void kernel_launch(void* const* d_in, const int* in_sizes, int n_in,
                              void* d_out, int out_size) {
    const float* x  = (const float*)d_in[0];
    const float* y  = (const float*)d_in[1];
    const float* wx = (const float*)d_in[2];
    const float* wy = (const float*)d_in[3];
    const float* wz = (const float*)d_in[4];
    float* out = (float*)d_out;

    host_compute_G();  // pure host math, deterministic, runs on every call
    gaunt_main_kernel<<<NBATCH, 128>>>(x, y, wx, wy, wz, out, h_G);
}

// round 5
// speedup vs baseline: 2.5091x; 1.0769x over previous
#include <cuda_runtime.h>
#include <utility>

#define RB 20
#define RA 19
#define MUL 128
#define NC 128
#define NBATCH 1024
#define D1 9
#define DZ 25
#define ZSTRIDE 28     // padded stride for 25-float z rows (112B, 16B aligned)
#define XYSTRIDE 20    // [xd1..8][yd1..8][xd0][yd0][pad][pad] (80B, 16B aligned)

// ===================== compile-time selection rules =====================
__host__ __device__ constexpr int lof(int d) {
    return (d < 1) ? 0 : (d < 4) ? 1 : (d < 9) ? 2 : (d < 16) ? 3 : 4;
}
__host__ __device__ constexpr bool gaunt_nz(int i, int j, int d) {
    const int l1 = lof(i), m1 = i - l1 * l1 - l1;
    const int l2 = lof(j), m2 = j - l2 * l2 - l2;
    const int L  = lof(d), M  = d - L * L - L;
    if ((l1 + l2 + L) & 1) return false;
    const int lo = (l1 > l2) ? (l1 - l2) : (l2 - l1);
    if (L < lo || L > l1 + l2) return false;
    const int f1 = m1 < 0 ? -m1 : m1;
    const int f2 = m2 < 0 ? -m2 : m2;
    const int F  = M  < 0 ? -M  : M;
    const int fd = (f1 > f2) ? (f1 - f2) : (f2 - f1);
    if (!(F == f1 + f2 || F == fd)) return false;
    if (((m1 < 0) + (m2 < 0) + (M < 0)) & 1) return false;
    return true;
}

// ===================== compile-time Gaunt table =====================
namespace cgaunt {

constexpr double PI = 3.14159265358979323846;

constexpr double csqrt(double x) {
    double r = (x > 1.0) ? x : 1.0;
    for (int i = 0; i < 80; ++i) r = 0.5 * (r + x / r);
    return r;
}
constexpr double redang(double x) {
    while (x >  PI) x -= 2.0 * PI;
    while (x < -PI) x += 2.0 * PI;
    return x;
}
constexpr double ccos(double x) {
    x = redang(x);
    double x2 = x * x, t = 1.0, s = 1.0;
    for (int k = 1; k <= 22; ++k) { t *= -x2 / ((2.0 * k - 1.0) * (2.0 * k)); s += t; }
    return s;
}
constexpr double csin(double x) {
    x = redang(x);
    double x2 = x * x, t = x, s = x;
    for (int k = 1; k <= 22; ++k) { t *= -x2 / ((2.0 * k) * (2.0 * k + 1.0)); s += t; }
    return s;
}
constexpr double cfact(int k) { double f = 1.0; for (int v = 2; v <= k; ++v) f *= v; return f; }

constexpr double alegP(int l, int m, double x) {
    double pmm = 1.0;
    if (m > 0) {
        double df = 1.0;
        for (int k = 1; k < 2 * m; k += 2) df *= (double)k;
        double somx2 = csqrt(1.0 - x * x);
        double s = 1.0;
        for (int k = 0; k < m; ++k) s *= somx2;
        pmm = ((m & 1) ? -1.0 : 1.0) * df * s;
    }
    if (l == m) return pmm;
    double pmmp1 = x * (2.0 * m + 1.0) * pmm;
    if (l == m + 1) return pmmp1;
    for (int ll = m + 2; ll <= l; ++ll) {
        double p = ((2.0 * ll - 1.0) * x * pmmp1 - (ll + m - 1.0) * pmm) / (double)(ll - m);
        pmm = pmmp1; pmmp1 = p;
    }
    return pmmp1;
}

struct GTab { double g[81][DZ]; };

constexpr GTab make_gaunt() {
    GTab T{};
    // Gauss-Legendre nodes/weights, degree 20, via Newton
    double ct[RB] = {}, qw[RB] = {};
    for (int i = 0; i < RB; ++i) {
        double xv = ccos(PI * (i + 0.75) / (RB + 0.5));
        double dp = 0.0;
        for (int it = 0; it < 60; ++it) {
            double p0 = 1.0, p1 = xv;
            for (int k = 2; k <= RB; ++k) {
                double p = ((2.0 * k - 1.0) * xv * p1 - (k - 1.0) * p0) / (double)k;
                p0 = p1; p1 = p;
            }
            dp = RB * (xv * p1 - p0) / (xv * xv - 1.0);
            xv -= p1 / dp;
        }
        {
            double p0 = 1.0, p1 = xv;
            for (int k = 2; k <= RB; ++k) {
                double p = ((2.0 * k - 1.0) * xv * p1 - (k - 1.0) * p0) / (double)k;
                p0 = p1; p1 = p;
            }
            dp = RB * (xv * p1 - p0) / (xv * xv - 1.0);
        }
        ct[i] = xv;
        qw[i] = 2.0 / ((1.0 - xv * xv) * dp * dp);
    }
    // normalized P (beta part) and angular part U, per d-index
    double Pn[DZ][RB] = {}, U[DZ][RA] = {};
    for (int d = 0; d < DZ; ++d) {
        int l = lof(d);
        int m = d - l * l - l;
        int am = m < 0 ? -m : m;
        double nlm = csqrt((2.0 * l + 1.0) / (4.0 * PI) * cfact(l - am) / cfact(l + am));
        for (int b = 0; b < RB; ++b) Pn[d][b] = nlm * alegP(l, am, ct[b]);
        for (int a = 0; a < RA; ++a) {
            double al = 2.0 * PI * (double)a / (double)RA;
            U[d][a] = (m == 0) ? 1.0
                    : (m > 0 ? csqrt(2.0) * ccos((double)m * al)
                             : csqrt(2.0) * csin((double)am * al));
        }
    }
    // folded scale: (2*pi/RA) quadrature * (1/sqrt(MUL))^2 * (1/sqrt(NC))
    const double scale = (2.0 * PI / (double)RA) / (double)MUL / csqrt((double)NC);
    for (int i = 0; i < 9; ++i)
        for (int j = 0; j < 9; ++j)
            for (int d = 0; d < DZ; ++d) {
                if (!gaunt_nz(i, j, d)) { T.g[i * 9 + j][d] = 0.0; continue; }
                double angs = 0.0;
                for (int a = 0; a < RA; ++a) angs += U[i][a] * U[j][a] * U[d][a];
                double bets = 0.0;
                for (int b = 0; b < RB; ++b) bets += qw[b] * Pn[i][b] * Pn[j][b] * Pn[d][b];
                T.g[i * 9 + j][d] = angs * bets * scale;
            }
    return T;
}

constexpr GTab GG = make_gaunt();

} // namespace cgaunt

// ===================== static_for (compile-time indices) =====================
template <typename F, int... Is>
__device__ __forceinline__ void sfor_impl(F&& f, std::integer_sequence<int, Is...>) {
    (f(std::integral_constant<int, Is>{}), ...);
}
template <int N, typename F>
__device__ __forceinline__ void sfor(F&& f) {
    sfor_impl(static_cast<F&&>(f), std::make_integer_sequence<int, N>{});
}

// ===================== packed f32x2 helpers =====================
__device__ __forceinline__ unsigned long long pk2(float lo, float hi) {
    unsigned long long r;
    asm("mov.b64 %0, {%1, %2};" : "=l"(r) : "f"(lo), "f"(hi));
    return r;
}
__device__ __forceinline__ void ffma2(unsigned long long& d,
                                      unsigned long long a, unsigned long long b) {
    asm("fma.rn.f32x2 %0, %1, %2, %0;" : "+l"(d) : "l"(a), "l"(b));
}
__device__ __forceinline__ void unpk2(unsigned long long v, float& lo, float& hi) {
    asm("mov.b64 {%0, %1}, %2;" : "=f"(lo), "=f"(hi) : "l"(v));
}

// ===================== pre-packed weights (device scratch) =====================
__device__ float4 WA[MUL * NC];    // (wx_l0, wx_l1, wx_l2, wy_l0) at [m*128+c]
__device__ float2 WB[MUL * NC];    // (wy_l1, wy_l2)
__device__ float4 WZ4[NC * NC];    // (wz_l0..wz_l3) at [cc*128+c]
__device__ float  WZ1[NC * NC];    // wz_l4

__global__ void pack_weights(const float* __restrict__ wx,
                             const float* __restrict__ wy,
                             const float* __restrict__ wz) {
    int idx = blockIdx.x * 256 + threadIdx.x;   // 0..16383 == m*128+c (or cc*128+c)
    WA[idx] = make_float4(wx[idx], wx[16384 + idx], wx[32768 + idx], wy[idx]);
    WB[idx] = make_float2(wy[16384 + idx], wy[32768 + idx]);
    WZ4[idx] = make_float4(wz[idx], wz[16384 + idx], wz[32768 + idx], wz[49152 + idx]);
    WZ1[idx] = wz[65536 + idx];
}

// ===================== main fused kernel =====================
__global__ void __launch_bounds__(128, 7)
gaunt_main_kernel(const float* __restrict__ x, const float* __restrict__ y,
                  float* __restrict__ out) {
    __shared__ __align__(16) float pool[NC * ZSTRIDE];   // 14336 B (xy rows, then zs)

    const int c = threadIdx.x;
    const int n = blockIdx.x;

    // ---- cooperative stage-in: xy row m = [xd1..8][yd1..8][xd0][yd0][pad2] ----
    const float* xg = x + (size_t)n * MUL * D1;
    const float* yg = y + (size_t)n * MUL * D1;
    #pragma unroll
    for (int it = 0; it < 9; ++it) {
        int idx = c + it * 128;
        int m = idx / 9, dd = idx - m * 9;
        float xv = xg[idx];
        float yv = yg[idx];
        int kx = (dd == 0) ? 16 : (dd - 1);
        int ky = (dd == 0) ? 17 : (7 + dd);
        pool[m * XYSTRIDE + kx] = xv;
        pool[m * XYSTRIDE + ky] = yv;
    }
    __syncthreads();

    // ---- stage 1: per-l linear in (packed f32x2, pre-packed weights) ----
    unsigned long long Ax[4], Ay[4];
    float sx = 0.0f, sy = 0.0f;
    #pragma unroll
    for (int k = 0; k < 4; ++k) { Ax[k] = Ay[k] = 0ULL; }

    #pragma unroll 4
    for (int m = 0; m < MUL; ++m) {
        float4 wa = WA[m * NC + c];
        float2 wb = WB[m * NC + c];
        const float* row = &pool[m * XYSTRIDE];
        float4 xv0 = *(const float4*)(row);       // xd1..xd4
        float4 xv1 = *(const float4*)(row + 4);   // xd5..xd8
        float4 yv0 = *(const float4*)(row + 8);   // yd1..yd4
        float4 yv1 = *(const float4*)(row + 12);  // yd5..yd8
        float2 d0  = *(const float2*)(row + 16);  // xd0, yd0

        ffma2(Ax[0], pk2(xv0.x, xv0.y), pk2(wa.y, wa.y));
        ffma2(Ax[1], pk2(xv0.z, xv0.w), pk2(wa.y, wa.z));
        ffma2(Ax[2], pk2(xv1.x, xv1.y), pk2(wa.z, wa.z));
        ffma2(Ax[3], pk2(xv1.z, xv1.w), pk2(wa.z, wa.z));
        sx += d0.x * wa.x;

        ffma2(Ay[0], pk2(yv0.x, yv0.y), pk2(wb.x, wb.x));
        ffma2(Ay[1], pk2(yv0.z, yv0.w), pk2(wb.x, wb.y));
        ffma2(Ay[2], pk2(yv1.x, yv1.y), pk2(wb.y, wb.y));
        ffma2(Ay[3], pk2(yv1.z, yv1.w), pk2(wb.y, wb.y));
        sy += d0.y * wa.w;
    }

    float xc[9], yc[9];
    xc[0] = sx; yc[0] = sy;
    #pragma unroll
    for (int k = 0; k < 4; ++k) {
        unpk2(Ax[k], xc[2 * k + 1], xc[2 * k + 2]);
        unpk2(Ay[k], yc[2 * k + 1], yc[2 * k + 2]);
    }

    // ---- stage 2: sparse Gaunt contraction with compile-time IMMEDIATE coeffs ----
    float z[DZ];
    #pragma unroll
    for (int d = 0; d < DZ; ++d) z[d] = 0.0f;

    sfor<9>([&](auto I) {
        constexpr int i = decltype(I)::value;
        sfor<9>([&](auto J) {
            constexpr int j = decltype(J)::value;
            float p = xc[i] * yc[j];
            sfor<DZ>([&](auto Dd) {
                constexpr int d = decltype(Dd)::value;
                if constexpr (gaunt_nz(i, j, d)) {
                    constexpr float gv = (float)cgaunt::GG.g[i * 9 + j][d];
                    z[d] = fmaf(p, gv, z[d]);
                }
            });
        });
    });

    __syncthreads();   // all warps done reading xy rows before zs overwrites pool

    // ---- z -> smem (vector stores, 28-float stride) ----
    {
        float* zr = &pool[c * ZSTRIDE];
        *(float4*)(zr)      = make_float4(z[0],  z[1],  z[2],  z[3]);
        *(float4*)(zr + 4)  = make_float4(z[4],  z[5],  z[6],  z[7]);
        *(float4*)(zr + 8)  = make_float4(z[8],  z[9],  z[10], z[11]);
        *(float4*)(zr + 12) = make_float4(z[12], z[13], z[14], z[15]);
        *(float4*)(zr + 16) = make_float4(z[16], z[17], z[18], z[19]);
        *(float4*)(zr + 20) = make_float4(z[20], z[21], z[22], z[23]);
        zr[24] = z[24];
    }
    __syncthreads();

    // ---- stage 3: per-l channel mixing, packed f32x2 ----
    unsigned long long a[12];
    float as = 0.0f;
    #pragma unroll
    for (int k = 0; k < 12; ++k) a[k] = 0ULL;

    #pragma unroll 2
    for (int cc = 0; cc < NC; ++cc) {
        float4 wv = WZ4[cc * NC + c];
        float  w4 = WZ1[cc * NC + c];
        const float* zp = &pool[cc * ZSTRIDE];
        float4 q0 = *(const float4*)(zp);
        float4 q1 = *(const float4*)(zp + 4);
        float4 q2 = *(const float4*)(zp + 8);
        float4 q3 = *(const float4*)(zp + 12);
        float4 q4 = *(const float4*)(zp + 16);
        float4 q5 = *(const float4*)(zp + 20);
        float  zl = zp[24];

        unsigned long long p01 = pk2(wv.x, wv.y);
        unsigned long long p11 = pk2(wv.y, wv.y);
        unsigned long long p22 = pk2(wv.z, wv.z);
        unsigned long long p23 = pk2(wv.z, wv.w);
        unsigned long long p33 = pk2(wv.w, wv.w);
        unsigned long long p44 = pk2(w4, w4);

        ffma2(a[0],  pk2(q0.x, q0.y), p01);
        ffma2(a[1],  pk2(q0.z, q0.w), p11);
        ffma2(a[2],  pk2(q1.x, q1.y), p22);
        ffma2(a[3],  pk2(q1.z, q1.w), p22);
        ffma2(a[4],  pk2(q2.x, q2.y), p23);
        ffma2(a[5],  pk2(q2.z, q2.w), p33);
        ffma2(a[6],  pk2(q3.x, q3.y), p33);
        ffma2(a[7],  pk2(q3.z, q3.w), p33);
        ffma2(a[8],  pk2(q4.x, q4.y), p44);
        ffma2(a[9],  pk2(q4.z, q4.w), p44);
        ffma2(a[10], pk2(q5.x, q5.y), p44);
        ffma2(a[11], pk2(q5.z, q5.w), p44);
        as += zl * w4;
    }

    // ---- write out (all scalar factors folded into G at compile time) ----
    float* og = out + ((size_t)n * NC + c) * DZ;
    #pragma unroll
    for (int k = 0; k < 12; ++k) {
        float lo, hi;
        unpk2(a[k], lo, hi);
        og[2 * k] = lo; og[2 * k + 1] = hi;
    }
    og[24] = as;
}

extern "C" void kernel_launch(void* const* d_in, const int* in_sizes, int n_in,
                              void* d_out, int out_size) {
    const float* x  = (const float*)d_in[0];
    const float* y  = (const float*)d_in[1];
    const float* wx = (const float*)d_in[2];
    const float* wy = (const float*)d_in[3];
    const float* wz = (const float*)d_in[4];
    float* out = (float*)d_out;

    pack_weights<<<64, 256>>>(wx, wy, wz);
    gaunt_main_kernel<<<NBATCH, 128>>>(x, y, out);
}